// round 17
// baseline (speedup 1.0000x reference)
#include <cuda_runtime.h>

#define BATCH 64
#define TT    200
#define NUM_C 2000
#define DIM   128
#define MM    50
#define MP    56          // M padded; rows 50..55 have w=0 (inert)
#define NX    4000        // distinct x = skill + 2000*answer

// ---------------- scratch (device globals; no allocation allowed) ----------
__device__ __align__(16) float g_w[NUM_C * MP];       // softmax(k·Mk^T) per skill id
__device__ __align__(16) float g_ea[NX * 256];        // [x][0:128]=e, [128:256]=a
__device__ __align__(16) float g_kf[NUM_C * DIM];     // k-part of f GEMM + f_b folded
__device__ __align__(16) float g_reads[BATCH * TT * DIM];
__device__ __align__(16) float g_fWat[DIM * DIM];     // [k][i] = f_W[i*256 + k]

__device__ __forceinline__ float sigmoidf_(float x) { return 1.f / (1.f + __expf(-x)); }

// =====================================================================
// w table v2: softmax(k_emb[c] · Mk^T); 63 CTAs x 32 skills.
// Mk^T fully resident (128x64, padded cols), 2 barriers total,
// warp-per-row softmax via shfl. exp(-1e30) -> 0 handles m>=50 pad.
// =====================================================================
#define WT_XP 129
#define WT_SMEM ((128 * 64 + 32 * WT_XP + 32 * 64) * 4)
__global__ __launch_bounds__(256) void k_wtable(const float* __restrict__ k_emb,
                                                const float* __restrict__ Mk) {
    extern __shared__ __align__(16) float wsm[];
    float* Wk = wsm;                       // [128][64]: Wk[k*64+m] = Mk[m][k]
    float* Xs = wsm + 128 * 64;            // [32][129]
    float* lg = Xs + 32 * WT_XP;           // [32][64] logits
    int row0 = blockIdx.x * 32;
    int tid = threadIdx.x;

    for (int idx = tid; idx < 128 * 64; idx += 256) {
        int m = idx >> 7, k = idx & 127;   // coalesced read from Mk
        Wk[k * 64 + m] = (m < MM) ? Mk[m * DIM + k] : 0.f;
    }
    for (int i = tid; i < 32 * DIM; i += 256) {
        int r = i >> 7, j = i & 127;
        int c = row0 + r;
        Xs[r * WT_XP + j] = (c < NUM_C) ? k_emb[c * DIM + j] : 0.f;
    }
    __syncthreads();

    int tx = tid & 15, ty = tid >> 4;      // cols tx*4.., rows ty*2..
    float acc[2][4];
    #pragma unroll
    for (int u = 0; u < 2; u++)
        #pragma unroll
        for (int v = 0; v < 4; v++) acc[u][v] = 0.f;
    #pragma unroll 8
    for (int k = 0; k < DIM; k++) {
        float4 w4 = *(const float4*)&Wk[k * 64 + tx * 4];
        float x0 = Xs[(ty * 2) * WT_XP + k];
        float x1 = Xs[(ty * 2 + 1) * WT_XP + k];
        acc[0][0] = fmaf(x0, w4.x, acc[0][0]);
        acc[0][1] = fmaf(x0, w4.y, acc[0][1]);
        acc[0][2] = fmaf(x0, w4.z, acc[0][2]);
        acc[0][3] = fmaf(x0, w4.w, acc[0][3]);
        acc[1][0] = fmaf(x1, w4.x, acc[1][0]);
        acc[1][1] = fmaf(x1, w4.y, acc[1][1]);
        acc[1][2] = fmaf(x1, w4.z, acc[1][2]);
        acc[1][3] = fmaf(x1, w4.w, acc[1][3]);
    }
    #pragma unroll
    for (int u = 0; u < 2; u++)
        #pragma unroll
        for (int v = 0; v < 4; v++) {
            int m = tx * 4 + v;
            lg[(ty * 2 + u) * 64 + m] = (m < MM) ? acc[u][v] : -1e30f;
        }
    __syncthreads();

    int wid = tid >> 5, lane = tid & 31;
    #pragma unroll
    for (int it = 0; it < 4; it++) {
        int r = wid + it * 8;
        int c = row0 + r;
        float v0 = lg[r * 64 + lane];
        float v1 = lg[r * 64 + 32 + lane];
        float mx = fmaxf(v0, v1);
        #pragma unroll
        for (int off = 16; off; off >>= 1) mx = fmaxf(mx, __shfl_xor_sync(~0u, mx, off));
        float e0 = __expf(v0 - mx);
        float e1 = __expf(v1 - mx);
        float sv = e0 + e1;
        #pragma unroll
        for (int off = 16; off; off >>= 1) sv += __shfl_xor_sync(~0u, sv, off);
        float inv = 1.f / sv;
        if (c < NUM_C) {
            g_w[c * MP + lane] = e0 * inv;
            if (lane < MP - 32) g_w[c * MP + 32 + lane] = e1 * inv;
        }
    }
}

// =====================================================================
// e/a table v2: 125 CTAs x 32 rows. FULL [128][256] weight block
// resident in dynamic smem (pitch 260), zero mainloop barriers.
// =====================================================================
#define EA_WP 260
#define EA_SMEM ((128 * EA_WP + 32 * DIM) * 4)
__global__ __launch_bounds__(256) void k_ea(const float* __restrict__ v_emb,
                                            const float* __restrict__ e_b,
                                            const float* __restrict__ a_b,
                                            const float* __restrict__ e_W,
                                            const float* __restrict__ a_W) {
    extern __shared__ __align__(16) float esm[];
    float* Ws = esm;                      // [128][260]: Ws[k*260+c]
    float* Xs = esm + 128 * EA_WP;        // [32][128]
    int row0 = blockIdx.x * 32;
    int tid = threadIdx.x;
    for (int idx = tid; idx < 256 * DIM; idx += 256) {
        int c = idx >> 7, k = idx & 127;  // coalesced read
        float v = (c < DIM) ? e_W[c * DIM + k] : a_W[(c - DIM) * DIM + k];
        Ws[k * EA_WP + c] = v;
    }
    for (int i = tid; i < 32 * DIM; i += 256) Xs[i] = v_emb[row0 * DIM + i];
    __syncthreads();

    int tx = tid & 31, ty = tid >> 5;     // cols tx*8, rows ty*4..
    float acc[4][8];
    #pragma unroll
    for (int u = 0; u < 4; u++)
        #pragma unroll
        for (int v = 0; v < 8; v++) acc[u][v] = 0.f;
    #pragma unroll 4
    for (int k = 0; k < DIM; k++) {
        float4 w0 = *(const float4*)&Ws[k * EA_WP + tx * 8];
        float4 w1 = *(const float4*)&Ws[k * EA_WP + tx * 8 + 4];
        float xv[4];
        #pragma unroll
        for (int u = 0; u < 4; u++) xv[u] = Xs[(ty * 4 + u) * DIM + k];
        #pragma unroll
        for (int u = 0; u < 4; u++) {
            acc[u][0] = fmaf(xv[u], w0.x, acc[u][0]);
            acc[u][1] = fmaf(xv[u], w0.y, acc[u][1]);
            acc[u][2] = fmaf(xv[u], w0.z, acc[u][2]);
            acc[u][3] = fmaf(xv[u], w0.w, acc[u][3]);
            acc[u][4] = fmaf(xv[u], w1.x, acc[u][4]);
            acc[u][5] = fmaf(xv[u], w1.y, acc[u][5]);
            acc[u][6] = fmaf(xv[u], w1.z, acc[u][6]);
            acc[u][7] = fmaf(xv[u], w1.w, acc[u][7]);
        }
    }
    int col = tx * 8;
    float barr[8];
    #pragma unroll
    for (int v = 0; v < 8; v++) {
        int cc = col + v;
        barr[v] = (cc < DIM) ? e_b[cc] : a_b[cc - DIM];
    }
    #pragma unroll
    for (int u = 0; u < 4; u++) {
        float o[8];
        #pragma unroll
        for (int v = 0; v < 8; v++) {
            float z = acc[u][v] + barr[v];
            o[v] = (col + v < DIM) ? sigmoidf_(z) : tanhf(z);
        }
        int r = row0 + ty * 4 + u;
        *(float4*)&g_ea[r * 256 + col]     = make_float4(o[0], o[1], o[2], o[3]);
        *(float4*)&g_ea[r * 256 + col + 4] = make_float4(o[4], o[5], o[6], o[7]);
    }
}

// =====================================================================
// kf table (63 CTAs) + f_W(reads-half) transpose (8 CTAs)
// =====================================================================
__global__ void k_kfT(const float* __restrict__ k_emb, const float* __restrict__ f_b,
                      const float* __restrict__ f_W) {
    __shared__ float Xs[32 * DIM];
    __shared__ __align__(16) float Ws[16 * 132];
    int bid = blockIdx.x;
    int tid = threadIdx.x;
    if (bid >= 63) {
        int base = (bid - 63) * 2048;
        #pragma unroll
        for (int j = 0; j < 8; j++) {
            int idx = base + j * 256 + tid;
            int k = idx >> 7, ii = idx & 127;
            g_fWat[idx] = f_W[ii * 256 + k];
        }
        return;
    }
    int row0 = bid * 32;
    for (int i = tid; i < 32 * DIM; i += 256) {
        int rr = i >> 7;
        Xs[i] = (row0 + rr < NUM_C) ? k_emb[row0 * DIM + i] : 0.f;
    }
    int tx = tid & 31, ty = tid >> 5;
    float acc[4][4];
    #pragma unroll
    for (int u = 0; u < 4; u++)
        #pragma unroll
        for (int v = 0; v < 4; v++) acc[u][v] = 0.f;
    for (int kc = 0; kc < DIM; kc += 16) {
        __syncthreads();
        for (int i = tid; i < 16 * DIM; i += 256) {
            int kk = i & 15, col = i >> 4;
            Ws[kk * 132 + col] = f_W[col * 256 + 128 + kc + kk];
        }
        __syncthreads();
        #pragma unroll
        for (int kk = 0; kk < 16; kk++) {
            float4 w0 = *(const float4*)&Ws[kk * 132 + tx * 4];
            #pragma unroll
            for (int u = 0; u < 4; u++) {
                float x = Xs[(ty * 4 + u) * DIM + kc + kk];
                acc[u][0] = fmaf(x, w0.x, acc[u][0]);
                acc[u][1] = fmaf(x, w0.y, acc[u][1]);
                acc[u][2] = fmaf(x, w0.z, acc[u][2]);
                acc[u][3] = fmaf(x, w0.w, acc[u][3]);
            }
        }
    }
    int col = tx * 4;
    float b0 = f_b[col], b1 = f_b[col + 1], b2 = f_b[col + 2], b3 = f_b[col + 3];
    #pragma unroll
    for (int u = 0; u < 4; u++) {
        int r = row0 + ty * 4 + u;
        if (r < NUM_C)
            *(float4*)&g_kf[r * DIM + col] =
                make_float4(acc[u][0] + b0, acc[u][1] + b1, acc[u][2] + b2, acc[u][3] + b3);
    }
}

// =====================================================================
// Scan (R9-proven, verbatim): 512 CTAs = 64 b x 8 d-slices of 16,
// 128 threads, 1 sync/step, depth-4 compile-time rotation.
// =====================================================================
__global__ __launch_bounds__(128) void k_scan(const int* __restrict__ skill,
                                              const int* __restrict__ answer,
                                              const float* __restrict__ Mv0) {
    __shared__ int s_sk[TT], s_x[TT];
    __shared__ __align__(16) float w_sh[4][MP];
    __shared__ __align__(16) float e_sh[4][16];
    __shared__ __align__(16) float a_sh[4][16];
    int b = blockIdx.x >> 3;
    int dbase = (blockIdx.x & 7) * 16;
    int tid = threadIdx.x;
    int wid = tid >> 5, lane = tid & 31;
    int mg = lane >> 2, dq = lane & 3;
    int dd = wid * 4 + dq;                 // 0..15 within slice

    for (int t = tid; t < TT; t += 128) {
        int s = skill[b * TT + t];
        int aa = answer[b * TT + t];
        if (aa > 1) aa = 1;
        s_sk[t] = s;
        s_x[t] = s + NUM_C * aa;
    }

    float mv[7];
    #pragma unroll
    for (int i = 0; i < 7; i++) {
        int m = mg * 7 + i;
        mv[i] = (m < MM) ? Mv0[m * DIM + dbase + dd] : 0.f;
    }
    __syncthreads();   // s_sk/s_x visible

    bool isW = tid < MP;
    bool isE = (tid >= 64) && (tid < 80);
    bool isA = (tid >= 80) && (tid < 96);
    bool lp = isW || isE || isA;
    int eoff = isE ? (dbase + (tid - 64)) : (128 + dbase + (tid - 80));

    float pfR[4];
    pfR[0] = 0.f; pfR[1] = 0.f; pfR[2] = 0.f; pfR[3] = 0.f;
    if (lp) {
        float v0;
        if (isW) {
            v0     = g_w[s_sk[0] * MP + tid];
            pfR[1] = g_w[s_sk[1] * MP + tid];
            pfR[2] = g_w[s_sk[2] * MP + tid];
            pfR[3] = g_w[s_sk[3] * MP + tid];
            w_sh[0][tid] = v0;
        } else {
            v0     = g_ea[s_x[0] * 256 + eoff];
            pfR[1] = g_ea[s_x[1] * 256 + eoff];
            pfR[2] = g_ea[s_x[2] * 256 + eoff];
            pfR[3] = g_ea[s_x[3] * 256 + eoff];
            if (isE) e_sh[0][tid - 64] = v0;
            else     a_sh[0][tid - 80] = v0;
        }
    }
    __syncthreads();

    int outbase = (b * TT) * DIM + dbase + dd;

    for (int t0 = 0; t0 < TT; t0 += 4) {
        #pragma unroll
        for (int q = 0; q < 4; q++) {
            int t = t0 + q;
            float e = e_sh[q][dd];
            float a = a_sh[q][dd];
            float acc = 0.f;
            #pragma unroll
            for (int i = 0; i < 7; i++) {
                float wm = w_sh[q][mg * 7 + i];
                acc = fmaf(wm, mv[i], acc);                      // PRE-update read
                mv[i] = fmaf(wm, fmaf(-e, mv[i], a), mv[i]);
            }
            acc += __shfl_xor_sync(~0u, acc, 4);
            acc += __shfl_xor_sync(~0u, acc, 8);
            acc += __shfl_xor_sync(~0u, acc, 16);
            if (mg == 0) g_reads[outbase + t * DIM] = acc;
            if (lp && t + 1 < TT) {
                float pv = pfR[(q + 1) & 3];
                int nb = (q + 1) & 3;
                if (isW)      w_sh[nb][tid] = pv;
                else if (isE) e_sh[nb][tid - 64] = pv;
                else          a_sh[nb][tid - 80] = pv;
            }
            if (lp && t + 4 < TT) {
                float nv;
                if (isW) nv = g_w[s_sk[t + 4] * MP + tid];
                else     nv = g_ea[s_x[t + 4] * 256 + eoff];
                pfR[q] = nv;
            }
            __syncthreads();
        }
    }
}

// =====================================================================
// fpred v2 (R14-proven): full fWat in 64KB dynamic smem, zero mainloop
// barriers. 199 CTAs x 64 rows, 256 threads.
// =====================================================================
#define FP_XPITCH 132
#define FP_SMEM ((64 * FP_XPITCH + DIM * DIM) * 4)
__global__ __launch_bounds__(256) void k_fpred(const int* __restrict__ skill,
                                               const float* __restrict__ p_W,
                                               const float* __restrict__ p_b,
                                               float* __restrict__ out) {
    extern __shared__ __align__(16) float dsm[];
    float* Xs = dsm;
    float* Ws = dsm + 64 * FP_XPITCH;
    __shared__ int s_kf[64], s_nx[64];
    int row0 = blockIdx.x * 64;
    int tid = threadIdx.x;

    if (tid < 64) {
        int r = row0 + tid;
        int bb = r / 199;
        int t = r - bb * 199;
        s_kf[tid] = skill[bb * TT + t];
        s_nx[tid] = skill[bb * TT + t + 1];
    }
    for (int i = tid * 4; i < DIM * DIM; i += 1024)
        *(float4*)&Ws[i] = *(const float4*)&g_fWat[i];
    {
        int row = tid >> 2, qr = tid & 3;
        int r = row0 + row;
        int bb = r / 199;
        int t = r - bb * 199;
        const float* src = &g_reads[(bb * TT + t) * DIM];
        #pragma unroll
        for (int j = 0; j < 8; j++) {
            int c4 = (qr + j * 4) * 4;
            *(float4*)&Xs[row * FP_XPITCH + c4] = *(const float4*)&src[c4];
        }
    }
    __syncthreads();

    int tx = tid & 15, ty = tid >> 4;
    float acc[4][8];
    #pragma unroll
    for (int u = 0; u < 4; u++)
        #pragma unroll
        for (int v = 0; v < 8; v++) acc[u][v] = 0.f;

    #pragma unroll 4
    for (int k = 0; k < DIM; k += 4) {
        float4 x0 = *(const float4*)&Xs[(ty * 4 + 0) * FP_XPITCH + k];
        float4 x1 = *(const float4*)&Xs[(ty * 4 + 1) * FP_XPITCH + k];
        float4 x2 = *(const float4*)&Xs[(ty * 4 + 2) * FP_XPITCH + k];
        float4 x3 = *(const float4*)&Xs[(ty * 4 + 3) * FP_XPITCH + k];
        #pragma unroll
        for (int kk = 0; kk < 4; kk++) {
            float4 w0 = *(const float4*)&Ws[(k + kk) * DIM + tx * 8];
            float4 w1 = *(const float4*)&Ws[(k + kk) * DIM + tx * 8 + 4];
            float xv[4];
            xv[0] = (kk == 0) ? x0.x : (kk == 1) ? x0.y : (kk == 2) ? x0.z : x0.w;
            xv[1] = (kk == 0) ? x1.x : (kk == 1) ? x1.y : (kk == 2) ? x1.z : x1.w;
            xv[2] = (kk == 0) ? x2.x : (kk == 1) ? x2.y : (kk == 2) ? x2.z : x2.w;
            xv[3] = (kk == 0) ? x3.x : (kk == 1) ? x3.y : (kk == 2) ? x3.z : x3.w;
            #pragma unroll
            for (int u = 0; u < 4; u++) {
                acc[u][0] = fmaf(xv[u], w0.x, acc[u][0]);
                acc[u][1] = fmaf(xv[u], w0.y, acc[u][1]);
                acc[u][2] = fmaf(xv[u], w0.z, acc[u][2]);
                acc[u][3] = fmaf(xv[u], w0.w, acc[u][3]);
                acc[u][4] = fmaf(xv[u], w1.x, acc[u][4]);
                acc[u][5] = fmaf(xv[u], w1.y, acc[u][5]);
                acc[u][6] = fmaf(xv[u], w1.z, acc[u][6]);
                acc[u][7] = fmaf(xv[u], w1.w, acc[u][7]);
            }
        }
    }
    __syncthreads();

    int col = tx * 8;
    #pragma unroll
    for (int u = 0; u < 4; u++) {
        int row = ty * 4 + u;
        int sc = s_kf[row];
        float4 k0 = *(const float4*)&g_kf[sc * DIM + col];
        float4 k1 = *(const float4*)&g_kf[sc * DIM + col + 4];
        Xs[row * FP_XPITCH + col + 0] = tanhf(acc[u][0] + k0.x);
        Xs[row * FP_XPITCH + col + 1] = tanhf(acc[u][1] + k0.y);
        Xs[row * FP_XPITCH + col + 2] = tanhf(acc[u][2] + k0.z);
        Xs[row * FP_XPITCH + col + 3] = tanhf(acc[u][3] + k0.w);
        Xs[row * FP_XPITCH + col + 4] = tanhf(acc[u][4] + k1.x);
        Xs[row * FP_XPITCH + col + 5] = tanhf(acc[u][5] + k1.y);
        Xs[row * FP_XPITCH + col + 6] = tanhf(acc[u][6] + k1.z);
        Xs[row * FP_XPITCH + col + 7] = tanhf(acc[u][7] + k1.w);
    }
    __syncthreads();

    int wid = tid >> 5, lane = tid & 31;
    for (int rr = wid * 8; rr < wid * 8 + 8; rr++) {
        int ns = s_nx[rr];
        int idx = (ns < NUM_C) ? ns : (NUM_C - 1);
        const float* pw = p_W + idx * DIM;
        float a = 0.f;
        #pragma unroll
        for (int q = 0; q < 4; q++)
            a = fmaf(Xs[rr * FP_XPITCH + lane + 32 * q], pw[lane + 32 * q], a);
        #pragma unroll
        for (int off = 16; off; off >>= 1) a += __shfl_xor_sync(~0u, a, off);
        if (lane == 0) {
            float pr = sigmoidf_(a + p_b[idx]);
            out[row0 + rr] = (ns < NUM_C) ? pr : 0.f;
        }
    }
}

// ---------------- launch: forked-capture stream graph ----------------------
extern "C" void kernel_launch(void* const* d_in, const int* in_sizes, int n_in,
                              void* d_out, int out_size) {
    const int*   skill  = (const int*)d_in[0];
    const int*   answer = (const int*)d_in[1];
    const float* k_emb  = (const float*)d_in[2];
    const float* v_emb  = (const float*)d_in[3];
    const float* Mk     = (const float*)d_in[4];
    const float* Mv0    = (const float*)d_in[5];
    const float* f_W    = (const float*)d_in[6];
    const float* f_b    = (const float*)d_in[7];
    const float* p_W    = (const float*)d_in[8];
    const float* p_b    = (const float*)d_in[9];
    const float* e_W    = (const float*)d_in[10];
    const float* e_b    = (const float*)d_in[11];
    const float* a_W    = (const float*)d_in[12];
    const float* a_b    = (const float*)d_in[13];
    float* out = (float*)d_out;

    static cudaStream_t sA = nullptr, sB = nullptr, sC = nullptr;
    static cudaEvent_t evR = nullptr, evA = nullptr, evB = nullptr, evC = nullptr;
    if (!sA) {   // first call = correctness run (not captured): safe to create
        cudaStreamCreateWithFlags(&sA, cudaStreamNonBlocking);
        cudaStreamCreateWithFlags(&sB, cudaStreamNonBlocking);
        cudaStreamCreateWithFlags(&sC, cudaStreamNonBlocking);
        cudaEventCreateWithFlags(&evR, cudaEventDisableTiming);
        cudaEventCreateWithFlags(&evA, cudaEventDisableTiming);
        cudaEventCreateWithFlags(&evB, cudaEventDisableTiming);
        cudaEventCreateWithFlags(&evC, cudaEventDisableTiming);
        cudaFuncSetAttribute(k_fpred, cudaFuncAttributeMaxDynamicSharedMemorySize, FP_SMEM);
        cudaFuncSetAttribute(k_wtable, cudaFuncAttributeMaxDynamicSharedMemorySize, WT_SMEM);
        cudaFuncSetAttribute(k_ea, cudaFuncAttributeMaxDynamicSharedMemorySize, EA_SMEM);
    }

    cudaEventRecord(evR, 0);
    cudaStreamWaitEvent(sA, evR, 0);
    cudaStreamWaitEvent(sB, evR, 0);
    cudaStreamWaitEvent(sC, evR, 0);

    k_wtable<<<63, 256, WT_SMEM, sA>>>(k_emb, Mk);
    k_ea    <<<125, 256, EA_SMEM, sB>>>(v_emb, e_b, a_b, e_W, a_W);
    k_kfT   <<<71, 256, 0, sC>>>(k_emb, f_b, f_W);      // overlaps scan

    cudaEventRecord(evA, sA);
    cudaEventRecord(evB, sB);
    cudaEventRecord(evC, sC);

    cudaStreamWaitEvent(0, evA, 0);
    cudaStreamWaitEvent(0, evB, 0);
    k_scan<<<512, 128>>>(skill, answer, Mv0);

    cudaStreamWaitEvent(0, evC, 0);
    k_fpred<<<199, 256, FP_SMEM>>>(skill, p_W, p_b, out);
}